// round 13
// baseline (speedup 1.0000x reference)
#include <cuda_runtime.h>
#include <cuda_bf16.h>
#include <cstdint>
#include <math.h>

typedef __nv_bfloat16 bf16;

#define NN 4096
#define CC 512
#define LL 64

// ---------------- scratch (device globals: no allocations allowed) ----------
__device__ bf16  g_adjb[(size_t)NN * NN];     // 32 MB  adj in bf16
__device__ bf16  g_Xhi[NN * CC];
__device__ bf16  g_Xlo[NN * CC];
__device__ bf16  g_Wfhi[CC * CC];
__device__ bf16  g_Wflo[CC * CC];
__device__ bf16  g_Wprojb[CC * LL];
__device__ bf16  g_Wpi1b[LL * CC];
__device__ bf16  g_stb[NN * CC];              // v[row] * target, bf16 (row-major)
__device__ float g_target[NN * CC];           // fp32 target
__device__ float g_q[NN];
__device__ float g_v[NN];
__device__ float g_d[NN];

// ---------------- PTX helpers ----------------------------------------------
__device__ __forceinline__ uint32_t smem_u32(const void* p) {
    return (uint32_t)__cvta_generic_to_shared(p);
}
__device__ __forceinline__ void cp_async16(uint32_t s, const void* g) {
    asm volatile("cp.async.cg.shared.global [%0], [%1], 16;\n" :: "r"(s), "l"(g) : "memory");
}
__device__ __forceinline__ void cp_commit() {
    asm volatile("cp.async.commit_group;\n" ::: "memory");
}
__device__ __forceinline__ void cp_wait0() {
    asm volatile("cp.async.wait_group 0;\n" ::: "memory");
}
__device__ __forceinline__ void cp_wait1() {
    asm volatile("cp.async.wait_group 1;\n" ::: "memory");
}
__device__ __forceinline__ void ldsm_x4(uint32_t* r, uint32_t a) {
    asm volatile("ldmatrix.sync.aligned.m8n8.x4.shared.b16 {%0,%1,%2,%3}, [%4];"
                 : "=r"(r[0]), "=r"(r[1]), "=r"(r[2]), "=r"(r[3]) : "r"(a));
}
__device__ __forceinline__ void ldsm_x2t(uint32_t* r, uint32_t a) {
    asm volatile("ldmatrix.sync.aligned.m8n8.x2.trans.shared.b16 {%0,%1}, [%2];"
                 : "=r"(r[0]), "=r"(r[1]) : "r"(a));
}
__device__ __forceinline__ void ldsm_x4t(uint32_t* r, uint32_t a) {
    asm volatile("ldmatrix.sync.aligned.m8n8.x4.trans.shared.b16 {%0,%1,%2,%3}, [%4];"
                 : "=r"(r[0]), "=r"(r[1]), "=r"(r[2]), "=r"(r[3]) : "r"(a));
}
__device__ __forceinline__ void mma_bf16(float* c, const uint32_t* a, const uint32_t* b) {
    asm volatile("mma.sync.aligned.m16n8k16.row.col.f32.bf16.bf16.f32 "
                 "{%0,%1,%2,%3}, {%4,%5,%6,%7}, {%8,%9}, {%0,%1,%2,%3};"
                 : "+f"(c[0]), "+f"(c[1]), "+f"(c[2]), "+f"(c[3])
                 : "r"(a[0]), "r"(a[1]), "r"(a[2]), "r"(a[3]), "r"(b[0]), "r"(b[1]));
}

// ---------------- fused pre-kernel: rowsum+convert(adj) AND bf16 conversions --
__global__ void k_pre(const float* __restrict__ adj, bf16* __restrict__ adjb,
                      float* __restrict__ q,
                      const float* __restrict__ x, const float* __restrict__ Wf,
                      const float* __restrict__ Wp, const float* __restrict__ Wp1,
                      bf16* __restrict__ Xhi, bf16* __restrict__ Xlo,
                      bf16* __restrict__ Wfhi, bf16* __restrict__ Wflo,
                      bf16* __restrict__ Wpb, bf16* __restrict__ Wp1b) {
    int t = threadIdx.x;
    if (blockIdx.x < NN) {
        int row = blockIdx.x;
        const float4* src = reinterpret_cast<const float4*>(adj + (size_t)row * NN);
        uint2* dst = reinterpret_cast<uint2*>(adjb + (size_t)row * NN);
        float s = 0.f;
#pragma unroll
        for (int i = 0; i < 4; i++) {
            float4 f = src[t + i * 256];
            s += (f.x + f.y) + (f.z + f.w);
            __nv_bfloat162 b0 = __floats2bfloat162_rn(f.x, f.y);
            __nv_bfloat162 b1 = __floats2bfloat162_rn(f.z, f.w);
            uint2 u;
            u.x = *reinterpret_cast<uint32_t*>(&b0);
            u.y = *reinterpret_cast<uint32_t*>(&b1);
            dst[t + i * 256] = u;
        }
        for (int o = 16; o > 0; o >>= 1) s += __shfl_xor_sync(0xffffffffu, s, o);
        __shared__ float ws[8];
        if ((t & 31) == 0) ws[t >> 5] = s;
        __syncthreads();
        if (t == 0) {
            float tot = 0.f;
#pragma unroll
            for (int i = 0; i < 8; i++) tot += ws[i];
            q[row] = tot;
        }
        return;
    }
    int i = (blockIdx.x - NN) * 256 + t;
    const int e0 = NN * CC;
    const int e1 = e0 + CC * CC;
    const int e2 = e1 + CC * LL;
    const int e3 = e2 + LL * CC;
    if (i < e0) {
        float f = x[i];
        bf16 h = __float2bfloat16(f);
        Xhi[i] = h;
        Xlo[i] = __float2bfloat16(f - __bfloat162float(h));
    } else if (i < e1) {
        int j = i - e0;
        float f = Wf[j];
        bf16 h = __float2bfloat16(f);
        Wfhi[j] = h;
        Wflo[j] = __float2bfloat16(f - __bfloat162float(h));
    } else if (i < e2) {
        int j = i - e1;
        Wpb[j] = __float2bfloat16(Wp[j]);
    } else if (i < e3) {
        int j = i - e2;
        Wp1b[j] = __float2bfloat16(Wp1[j]);
    }
}

// ---------------- fused MLP (known-good) -------------------------------------
__global__ void __launch_bounds__(256)
k_mlp(const bf16* __restrict__ X, const bf16* __restrict__ Wp,
      const float* __restrict__ bproj,
      const bf16* __restrict__ Wp1, const float* __restrict__ bpi1,
      const float* __restrict__ W2, const float* __restrict__ b2,
      const float* __restrict__ q, float* __restrict__ v) {
    extern __shared__ __align__(16) char smm[];
    bf16* Zs = (bf16*)smm;              // [128][72]
    bf16* Xs = Zs + 128 * 72;           // [2][128][72]   (phase2: reused as Bs2)
    bf16* Ws = Xs + 2 * 128 * 72;       // [2][64][72]
    float* scal = (float*)(Ws + 2 * 64 * 72);  // [256]

    const int tid = threadIdx.x, lane = tid & 31, wm = tid >> 5;
    const int bm0 = blockIdx.x * 128;

    float accz[8][4];
#pragma unroll
    for (int j = 0; j < 8; j++)
#pragma unroll
        for (int k = 0; k < 4; k++) accz[j][k] = 0.f;

    auto ld1 = [&](int kt, int buf) {
#pragma unroll
        for (int c0 = 0; c0 < 1024; c0 += 256) {
            int c = c0 + tid;
            int r = c >> 3, co = (c & 7) * 8;
            cp_async16(smem_u32(Xs + buf * 9216 + r * 72 + co),
                       X + (size_t)(bm0 + r) * CC + kt * 64 + co);
        }
#pragma unroll
        for (int c0 = 0; c0 < 512; c0 += 256) {
            int c = c0 + tid;
            int r = c >> 3, co = (c & 7) * 8;
            cp_async16(smem_u32(Ws + buf * 4608 + r * 72 + co),
                       Wp + (size_t)(kt * 64 + r) * LL + co);
        }
    };

    ld1(0, 0);
    cp_commit();
    for (int kt = 0; kt < 8; ++kt) {
        int buf = kt & 1;
        cp_wait0();
        __syncthreads();
        if (kt < 7) {
            ld1(kt + 1, buf ^ 1);
            cp_commit();
        }
#pragma unroll
        for (int kk = 0; kk < 4; ++kk) {
            uint32_t a[4];
            ldsm_x4(a, smem_u32(Xs + buf * 9216 + (wm * 16 + (lane & 15)) * 72 +
                                kk * 16 + ((lane >> 4) << 3)));
#pragma unroll
            for (int j = 0; j < 8; j++) {
                uint32_t b[2];
                ldsm_x2t(b, smem_u32(Ws + buf * 4608 + (kk * 16 + (lane & 15)) * 72 + j * 8));
                mma_bf16(accz[j], a, b);
            }
        }
        __syncthreads();
    }

#pragma unroll
    for (int j = 0; j < 8; j++)
#pragma unroll
        for (int h = 0; h < 2; h++) {
            int r = wm * 16 + (lane >> 2) + 8 * h;
            int c = j * 8 + (lane & 3) * 2;
            float z0 = accz[j][2 * h + 0] + bproj[c];
            float z1 = accz[j][2 * h + 1] + bproj[c + 1];
            *reinterpret_cast<__nv_bfloat162*>(Zs + r * 72 + c) =
                __floats2bfloat162_rn(z0, z1);
        }
    __syncthreads();

    bf16* Bs2 = Xs;
    float pia[2] = {0.f, 0.f};
    for (int nt = 0; nt < 4; ++nt) {
        int n0 = nt * 128;
#pragma unroll
        for (int c0 = 0; c0 < 1024; c0 += 256) {
            int c = c0 + tid;
            int r = c >> 4, co = (c & 15) * 8;
            cp_async16(smem_u32(Bs2 + r * 136 + co),
                       Wp1 + (size_t)r * CC + n0 + co);
        }
        if (tid < 128) scal[tid] = bpi1[n0 + tid];
        else           scal[tid] = W2[n0 + tid - 128];
        cp_commit();
        cp_wait0();
        __syncthreads();

        float acc2[16][4];
#pragma unroll
        for (int j = 0; j < 16; j++)
#pragma unroll
            for (int k = 0; k < 4; k++) acc2[j][k] = 0.f;
#pragma unroll
        for (int kk = 0; kk < 4; ++kk) {
            uint32_t a[4];
            ldsm_x4(a, smem_u32(Zs + (wm * 16 + (lane & 15)) * 72 +
                                kk * 16 + ((lane >> 4) << 3)));
#pragma unroll
            for (int j = 0; j < 16; j++) {
                uint32_t b[2];
                ldsm_x2t(b, smem_u32(Bs2 + (kk * 16 + (lane & 15)) * 136 + j * 8));
                mma_bf16(acc2[j], a, b);
            }
        }
#pragma unroll
        for (int j = 0; j < 16; j++)
#pragma unroll
            for (int h = 0; h < 2; h++) {
                int c = j * 8 + (lane & 3) * 2;
                float h0 = fmaxf(acc2[j][2 * h + 0] + scal[c], 0.f);
                float h1 = fmaxf(acc2[j][2 * h + 1] + scal[c + 1], 0.f);
                pia[h] += h0 * scal[128 + c] + h1 * scal[128 + c + 1];
            }
        __syncthreads();
    }

#pragma unroll
    for (int h = 0; h < 2; h++) {
        pia[h] += __shfl_xor_sync(0xffffffffu, pia[h], 1);
        pia[h] += __shfl_xor_sync(0xffffffffu, pia[h], 2);
    }
    if ((lane & 3) == 0) {
        float bb = b2[0];
#pragma unroll
        for (int h = 0; h < 2; h++) {
            int row = bm0 + wm * 16 + (lane >> 2) + 8 * h;
            float s = pia[h] + bb;
            float pi = 1.f / (1.f + expf(-s));
            v[row] = pi / q[row];
        }
    }
}

// d[i] = sum_j adjb[i,j] * v[j] + 1e-5
__global__ void k_dvec(const bf16* __restrict__ adjb, const float* __restrict__ v,
                       float* __restrict__ d) {
    int row = blockIdx.x, t = threadIdx.x;  // 256 threads
    const uint4* ap = reinterpret_cast<const uint4*>(adjb + (size_t)row * NN);
    float s = 0.f;
#pragma unroll
    for (int i = 0; i < 2; i++) {
        int ci = t + i * 256;
        uint4 u = ap[ci];
        const float4* vp = reinterpret_cast<const float4*>(v + ci * 8);
        float4 v0 = vp[0], v1 = vp[1];
        __nv_bfloat162 a0 = *reinterpret_cast<__nv_bfloat162*>(&u.x);
        __nv_bfloat162 a1 = *reinterpret_cast<__nv_bfloat162*>(&u.y);
        __nv_bfloat162 a2 = *reinterpret_cast<__nv_bfloat162*>(&u.z);
        __nv_bfloat162 a3 = *reinterpret_cast<__nv_bfloat162*>(&u.w);
        s += __bfloat162float(a0.x) * v0.x + __bfloat162float(a0.y) * v0.y +
             __bfloat162float(a1.x) * v0.z + __bfloat162float(a1.y) * v0.w +
             __bfloat162float(a2.x) * v1.x + __bfloat162float(a2.y) * v1.y +
             __bfloat162float(a3.x) * v1.z + __bfloat162float(a3.y) * v1.w;
    }
    for (int o = 16; o > 0; o >>= 1) s += __shfl_xor_sync(0xffffffffu, s, o);
    __shared__ float ws[8];
    if ((t & 31) == 0) ws[t >> 5] = s;
    __syncthreads();
    if (t == 0) {
        float tot = 0.f;
#pragma unroll
        for (int i = 0; i < 8; i++) tot += ws[i];
        d[row] = tot + 1e-5f;
    }
}

// ---------------- split-bf16 GEMM (R10 best version: 256 thr, 2-stage) -------
__global__ void __launch_bounds__(256)
gemm_split3(const bf16* __restrict__ Ah, const bf16* __restrict__ Al,
            const bf16* __restrict__ Bh, const bf16* __restrict__ Bl,
            const float* __restrict__ bias, const float* __restrict__ vvec,
            float* __restrict__ outf, bf16* __restrict__ outb) {
    constexpr int BM = 128, BN = 128, BK = 32, WMC = 2, WNC = 4;
    constexpr int WARP_M = BM / WMC, WARP_N = BN / WNC;   // 64, 32
    constexpr int FM = WARP_M / 16, FN = WARP_N / 8;      // 4, 4
    constexpr int LDA = BK + 8, LDB = BN + 8;             // 40, 136
    constexpr int ASTG = BM * LDA;                        // 5120
    constexpr int BSTG = BK * LDB;                        // 4352
    extern __shared__ __align__(16) char sm3[];
    bf16* Ahs = (bf16*)sm3;              // [2][ASTG]
    bf16* Als = Ahs + 2 * ASTG;
    bf16* Bhs = Als + 2 * ASTG;
    bf16* Bls = Bhs + 2 * BSTG;

    const int tid = threadIdx.x, lane = tid & 31, warp = tid >> 5;
    const int wm = warp / WNC, wn = warp % WNC;
    const int bm0 = blockIdx.x * BM, bn0 = blockIdx.y * BN;
    constexpr int ACH = BM * BK / 8, BCH = BK * BN / 8;   // 512, 512

    float acc[FM][FN][4];
#pragma unroll
    for (int i = 0; i < FM; i++)
#pragma unroll
        for (int j = 0; j < FN; j++)
#pragma unroll
            for (int k = 0; k < 4; k++) acc[i][j][k] = 0.f;

    auto load_tiles = [&](int kt, int buf) {
        for (int c = tid; c < ACH; c += 256) {
            int r = c / 4, co = (c % 4) * 8;
            size_t g = (size_t)(bm0 + r) * CC + (size_t)kt * BK + co;
            cp_async16(smem_u32(Ahs + buf * ASTG + r * LDA + co), Ah + g);
            cp_async16(smem_u32(Als + buf * ASTG + r * LDA + co), Al + g);
        }
        for (int c = tid; c < BCH; c += 256) {
            int r = c / 16, co = (c % 16) * 8;
            size_t g = (size_t)(kt * BK + r) * CC + bn0 + co;
            cp_async16(smem_u32(Bhs + buf * BSTG + r * LDB + co), Bh + g);
            cp_async16(smem_u32(Bls + buf * BSTG + r * LDB + co), Bl + g);
        }
    };

    const int KTL = CC / BK;   // 16
    load_tiles(0, 0);
    cp_commit();
    for (int it = 0; it < KTL; ++it) {
        int buf = it & 1;
        cp_wait0();
        __syncthreads();
        if (it + 1 < KTL) {
            load_tiles(it + 1, buf ^ 1);
            cp_commit();
        }
#pragma unroll
        for (int kk = 0; kk < BK / 16; ++kk) {
            uint32_t ahf[FM][4], alf[FM][4], bhf[FN][2], blf[FN][2];
#pragma unroll
            for (int i = 0; i < FM; i++) {
                int r = wm * WARP_M + i * 16 + (lane & 15);
                int cc = kk * 16 + ((lane >> 4) << 3);
                ldsm_x4(ahf[i], smem_u32(Ahs + buf * ASTG + r * LDA + cc));
                ldsm_x4(alf[i], smem_u32(Als + buf * ASTG + r * LDA + cc));
            }
#pragma unroll
            for (int j = 0; j < FN; j++) {
                int r = kk * 16 + (lane & 15);
                int cc = wn * WARP_N + j * 8;
                ldsm_x2t(bhf[j], smem_u32(Bhs + buf * BSTG + r * LDB + cc));
                ldsm_x2t(blf[j], smem_u32(Bls + buf * BSTG + r * LDB + cc));
            }
#pragma unroll
            for (int i = 0; i < FM; i++)
#pragma unroll
                for (int j = 0; j < FN; j++) {
                    mma_bf16(acc[i][j], ahf[i], bhf[j]);
                    mma_bf16(acc[i][j], ahf[i], blf[j]);
                    mma_bf16(acc[i][j], alf[i], bhf[j]);
                }
        }
        __syncthreads();
    }

#pragma unroll
    for (int i = 0; i < FM; i++) {
        int rbase = bm0 + wm * WARP_M + i * 16 + (lane >> 2);
#pragma unroll
        for (int h = 0; h < 2; h++) {
            int r = rbase + h * 8;
            float vr = vvec[r];
#pragma unroll
            for (int j = 0; j < FN; j++) {
                int c = bn0 + wn * WARP_N + j * 8 + (lane & 3) * 2;
                float x0 = fmaxf(acc[i][j][h * 2 + 0] + bias[c], 0.f);
                float x1 = fmaxf(acc[i][j][h * 2 + 1] + bias[c + 1], 0.f);
                size_t idx = (size_t)r * CC + c;
                *reinterpret_cast<float2*>(outf + idx) = make_float2(x0, x1);
                *reinterpret_cast<__nv_bfloat162*>(outb + idx) =
                    __floats2bfloat162_rn(vr * x0, vr * x1);
            }
        }
    }
}

// ---------------- final GEMM: 2 warps/CTA, warp tile 64x64 (FM=4, FN=8) ------
// out[m, n] = (1-dt)*tgt[m, n] + dt/(0.25*d[m]) * sum_k adjb[m, k] * stb[k, n]
// BM=128 BN=64 BK=64; 64 threads; 3-stage; 2 CTAs/SM; grid 32x8=256.
// LDSM bytes per MMA: 512/FN + 256/FM = 128B (was 192B) -> -33% smem traffic.
__global__ void __launch_bounds__(64, 2)
k_final(const bf16* __restrict__ A, const bf16* __restrict__ B,
        const float* __restrict__ dvec, const float* __restrict__ tgt,
        const float* __restrict__ dtp, float* __restrict__ outf) {
    constexpr int BM = 128, BN = 64, BK = 64;
    constexpr int FM = 4, FN = 8;                         // warp tile 64x64
    constexpr int LDA = BK + 8, LDB = BN + 8;             // 72, 72
    constexpr int ASTG = BM * LDA;                        // 9216
    constexpr int BSTG = BK * LDB;                        // 4608
    extern __shared__ __align__(16) char smf[];
    bf16* As = (bf16*)smf;               // [3][ASTG]
    bf16* Bs = As + 3 * ASTG;            // [3][BSTG]

    const int tid = threadIdx.x, lane = tid & 31, warp = tid >> 5;  // warp 0/1
    const int bm0 = blockIdx.x * BM, bn0 = blockIdx.y * BN;
    constexpr int ACH = BM * BK / 8, BCH = BK * BN / 8;   // 1024, 512

    float acc[FM][FN][4];
#pragma unroll
    for (int i = 0; i < FM; i++)
#pragma unroll
        for (int j = 0; j < FN; j++)
#pragma unroll
            for (int k = 0; k < 4; k++) acc[i][j][k] = 0.f;

    auto load_tiles = [&](int kt, int buf) {
#pragma unroll
        for (int c0 = 0; c0 < ACH; c0 += 64) {
            int c = c0 + tid;
            int r = c / 8, co = (c % 8) * 8;
            cp_async16(smem_u32(As + buf * ASTG + r * LDA + co),
                       A + (size_t)(bm0 + r) * NN + (size_t)kt * BK + co);
        }
#pragma unroll
        for (int c0 = 0; c0 < BCH; c0 += 64) {
            int c = c0 + tid;
            int r = c / 8, co = (c % 8) * 8;
            cp_async16(smem_u32(Bs + buf * BSTG + r * LDB + co),
                       B + (size_t)(kt * BK + r) * CC + bn0 + co);
        }
    };

    const int KTL = NN / BK;   // 64
    load_tiles(0, 0); cp_commit();
    load_tiles(1, 1); cp_commit();

    for (int it = 0; it < KTL; ++it) {
        int buf = it % 3;
        if (it + 1 < KTL) cp_wait1();
        else              cp_wait0();
        __syncthreads();
        if (it + 2 < KTL) {
            load_tiles(it + 2, (it + 2) % 3);
            cp_commit();
        }
#pragma unroll
        for (int kk = 0; kk < BK / 16; ++kk) {
            uint32_t af[FM][4], bfr[FN][2];
#pragma unroll
            for (int i = 0; i < FM; i++) {
                int r = warp * 64 + i * 16 + (lane & 15);
                int cc = kk * 16 + ((lane >> 4) << 3);
                ldsm_x4(af[i], smem_u32(As + buf * ASTG + r * LDA + cc));
            }
            // B: 8 n-tiles of 8 cols; use x4t pairs to halve instruction count
#pragma unroll
            for (int j = 0; j < FN; j += 2) {
                uint32_t b4[4];
                int r = kk * 16 + (lane & 15);
                int cc = j * 8 + ((lane >> 4) << 3);
                ldsm_x4t(b4, smem_u32(Bs + buf * BSTG + r * LDB + cc));
                bfr[j][0] = b4[0]; bfr[j][1] = b4[1];
                bfr[j + 1][0] = b4[2]; bfr[j + 1][1] = b4[3];
            }
#pragma unroll
            for (int i = 0; i < FM; i++)
#pragma unroll
                for (int j = 0; j < FN; j++) mma_bf16(acc[i][j], af[i], bfr[j]);
        }
        __syncthreads();
    }

    const float dt1 = dtp[0];
    const float mdt = 1.f - dt1;
#pragma unroll
    for (int i = 0; i < FM; i++) {
        int rbase = bm0 + warp * 64 + i * 16 + (lane >> 2);
#pragma unroll
        for (int h = 0; h < 2; h++) {
            int r = rbase + h * 8;
            float rs = dt1 / (0.25f * dvec[r]);
#pragma unroll
            for (int j = 0; j < FN; j++) {
                int c = bn0 + j * 8 + (lane & 3) * 2;
                size_t idx = (size_t)r * CC + c;
                float2 tg = *reinterpret_cast<const float2*>(tgt + idx);
                float2 o;
                o.x = mdt * tg.x + rs * acc[i][j][h * 2 + 0];
                o.y = mdt * tg.y + rs * acc[i][j][h * 2 + 1];
                *reinterpret_cast<float2*>(outf + idx) = o;
            }
        }
    }
}

// ---------------- host -------------------------------------------------------
extern "C" void kernel_launch(void* const* d_in, const int* in_sizes, int n_in,
                              void* d_out, int out_size) {
    const float* x      = (const float*)d_in[0];
    const float* adj    = (const float*)d_in[1];
    const float* W_proj = (const float*)d_in[2];
    const float* b_proj = (const float*)d_in[3];
    const float* W_pi1  = (const float*)d_in[4];
    const float* b_pi1  = (const float*)d_in[5];
    const float* W_pi2  = (const float*)d_in[6];
    const float* b_pi2  = (const float*)d_in[7];
    const float* W_f    = (const float*)d_in[8];
    const float* b_f    = (const float*)d_in[9];
    const float* dt     = (const float*)d_in[10];
    float* out = (float*)d_out;
    (void)in_sizes; (void)n_in; (void)out_size;

    void *p_adjb, *p_xhi, *p_xlo, *p_wfhi, *p_wflo, *p_wprojb, *p_wpi1b;
    void *p_stb, *p_tgt, *p_q, *p_v, *p_d;
    cudaGetSymbolAddress(&p_adjb, g_adjb);
    cudaGetSymbolAddress(&p_xhi, g_Xhi);
    cudaGetSymbolAddress(&p_xlo, g_Xlo);
    cudaGetSymbolAddress(&p_wfhi, g_Wfhi);
    cudaGetSymbolAddress(&p_wflo, g_Wflo);
    cudaGetSymbolAddress(&p_wprojb, g_Wprojb);
    cudaGetSymbolAddress(&p_wpi1b, g_Wpi1b);
    cudaGetSymbolAddress(&p_stb, g_stb);
    cudaGetSymbolAddress(&p_tgt, g_target);
    cudaGetSymbolAddress(&p_q, g_q);
    cudaGetSymbolAddress(&p_v, g_v);
    cudaGetSymbolAddress(&p_d, g_d);

    bf16* adjb = (bf16*)p_adjb;
    bf16 *Xhi = (bf16*)p_xhi, *Xlo = (bf16*)p_xlo;
    bf16 *Wfhi = (bf16*)p_wfhi, *Wflo = (bf16*)p_wflo;
    bf16 *Wprojb = (bf16*)p_wprojb, *Wpi1b = (bf16*)p_wpi1b;
    bf16 *stb = (bf16*)p_stb;
    float *tgt = (float*)p_tgt, *q = (float*)p_q, *v = (float*)p_v, *d = (float*)p_d;

    // dynamic smem opt-ins (idempotent)
    const int SMM = (128 * 72 + 2 * 128 * 72 + 2 * 64 * 72) * 2 + 1024;  // 74,752 B
    const int SM3 = (2 * 5120 * 2 + 2 * 4352 * 2) * 2;                    // 75,776 B
    const int SMF = 3 * (9216 + 4608) * 2;                                // 82,944 B
    cudaFuncSetAttribute(k_mlp, cudaFuncAttributeMaxDynamicSharedMemorySize, SMM);
    cudaFuncSetAttribute(gemm_split3, cudaFuncAttributeMaxDynamicSharedMemorySize, SM3);
    cudaFuncSetAttribute(k_final, cudaFuncAttributeMaxDynamicSharedMemorySize, SMF);

    // 1. fused pre: rowsum+convert adj, split x/W_f, convert W_proj/W_pi1
    {
        const int conv_tot = NN * CC + CC * CC + CC * LL + LL * CC;
        const int conv_blocks = (conv_tot + 255) / 256;
        k_pre<<<NN + conv_blocks, 256>>>(adj, adjb, q, x, W_f, W_proj, W_pi1,
                                         Xhi, Xlo, Wfhi, Wflo, Wprojb, Wpi1b);
    }

    // 2. fused MLP: Z, H (in regs), pi, v = pi/q
    k_mlp<<<NN / 128, 256, SMM>>>(Xhi, Wprojb, b_proj, Wpi1b, b_pi1,
                                  W_pi2, b_pi2, q, v);

    // 3. d = adjb @ v + 1e-5
    k_dvec<<<NN, 256>>>(adjb, v, d);

    // 4. target = relu(x @ W_f + b_f) fp32-accurate; stb = v[r]*target (bf16)
    gemm_split3<<<dim3(NN / 128, CC / 128), 256, SM3>>>(
        Xhi, Xlo, Wfhi, Wflo, b_f, v, tgt, stb);

    // 5. out = (1-dt)*target + (dt/(eps*d[m])) * (adjb @ stb)
    k_final<<<dim3(NN / 128, CC / 64), 64, SMF>>>(adjb, stb, d, tgt, dt, out);
}

// round 14
// speedup vs baseline: 1.0899x; 1.0899x over previous
#include <cuda_runtime.h>
#include <cuda_bf16.h>
#include <cstdint>
#include <math.h>

typedef __nv_bfloat16 bf16;

#define NN 4096
#define CC 512
#define LL 64

#define GEMM_BLKS 128        // split3-target blocks (32 x 4)
#define MLP_BLKS  32

// ---------------- scratch (device globals: no allocations allowed) ----------
__device__ bf16  g_adjb[(size_t)NN * NN];     // 32 MB  adj in bf16
__device__ bf16  g_Xhi[NN * CC];
__device__ bf16  g_Xlo[NN * CC];
__device__ bf16  g_Wfhi[CC * CC];
__device__ bf16  g_Wflo[CC * CC];
__device__ bf16  g_Wprojb[CC * LL];
__device__ bf16  g_Wpi1b[LL * CC];
__device__ bf16  g_stb[NN * CC];              // v[row] * target, bf16 (row-major)
__device__ float g_target[NN * CC];           // fp32 target
__device__ float g_q[NN];
__device__ float g_pi[NN];
__device__ float g_v[NN];
__device__ float g_d[NN];

// ---------------- PTX helpers ----------------------------------------------
__device__ __forceinline__ uint32_t smem_u32(const void* p) {
    return (uint32_t)__cvta_generic_to_shared(p);
}
__device__ __forceinline__ void cp_async16(uint32_t s, const void* g) {
    asm volatile("cp.async.cg.shared.global [%0], [%1], 16;\n" :: "r"(s), "l"(g) : "memory");
}
__device__ __forceinline__ void cp_commit() {
    asm volatile("cp.async.commit_group;\n" ::: "memory");
}
__device__ __forceinline__ void cp_wait0() {
    asm volatile("cp.async.wait_group 0;\n" ::: "memory");
}
__device__ __forceinline__ void cp_wait1() {
    asm volatile("cp.async.wait_group 1;\n" ::: "memory");
}
__device__ __forceinline__ void ldsm_x4(uint32_t* r, uint32_t a) {
    asm volatile("ldmatrix.sync.aligned.m8n8.x4.shared.b16 {%0,%1,%2,%3}, [%4];"
                 : "=r"(r[0]), "=r"(r[1]), "=r"(r[2]), "=r"(r[3]) : "r"(a));
}
__device__ __forceinline__ void ldsm_x2t(uint32_t* r, uint32_t a) {
    asm volatile("ldmatrix.sync.aligned.m8n8.x2.trans.shared.b16 {%0,%1}, [%2];"
                 : "=r"(r[0]), "=r"(r[1]) : "r"(a));
}
__device__ __forceinline__ void mma_bf16(float* c, const uint32_t* a, const uint32_t* b) {
    asm volatile("mma.sync.aligned.m16n8k16.row.col.f32.bf16.bf16.f32 "
                 "{%0,%1,%2,%3}, {%4,%5,%6,%7}, {%8,%9}, {%0,%1,%2,%3};"
                 : "+f"(c[0]), "+f"(c[1]), "+f"(c[2]), "+f"(c[3])
                 : "r"(a[0]), "r"(a[1]), "r"(a[2]), "r"(a[3]), "r"(b[0]), "r"(b[1]));
}

// ---------------- tiny conversion kernel (precedes the mega kernel) ---------
__global__ void k_conv(const float* __restrict__ x, const float* __restrict__ Wf,
                       const float* __restrict__ Wp, const float* __restrict__ Wp1,
                       bf16* __restrict__ Xhi, bf16* __restrict__ Xlo,
                       bf16* __restrict__ Wfhi, bf16* __restrict__ Wflo,
                       bf16* __restrict__ Wpb, bf16* __restrict__ Wp1b) {
    int i = blockIdx.x * 256 + threadIdx.x;
    const int e0 = NN * CC;
    const int e1 = e0 + CC * CC;
    const int e2 = e1 + CC * LL;
    const int e3 = e2 + LL * CC;
    if (i < e0) {
        float f = x[i];
        bf16 h = __float2bfloat16(f);
        Xhi[i] = h;
        Xlo[i] = __float2bfloat16(f - __bfloat162float(h));
    } else if (i < e1) {
        int j = i - e0;
        float f = Wf[j];
        bf16 h = __float2bfloat16(f);
        Wfhi[j] = h;
        Wflo[j] = __float2bfloat16(f - __bfloat162float(h));
    } else if (i < e2) {
        int j = i - e1;
        Wpb[j] = __float2bfloat16(Wp[j]);
    } else if (i < e3) {
        int j = i - e2;
        Wp1b[j] = __float2bfloat16(Wp1[j]);
    }
}

// ---------------- MEGA kernel: 3 independent block types ---------------------
// blocks [0, 128):        split3 target GEMM  (tensor-bound)
// blocks [128, 160):      MLP -> pi           (tensor, small)
// blocks [160, 160+4096): adj rowsum + bf16 convert (DRAM-bound)
// All three are mutually independent; DRAM streaming of the adj blocks hides
// under the tensor work of the GEMM blocks within the same wave.
__global__ void __launch_bounds__(256)
k_mega(const float* __restrict__ adj, bf16* __restrict__ adjb, float* __restrict__ q,
       const bf16* __restrict__ Ah, const bf16* __restrict__ Al,
       const bf16* __restrict__ Bh, const bf16* __restrict__ Bl,
       const float* __restrict__ bias, float* __restrict__ outf,
       const bf16* __restrict__ X, const bf16* __restrict__ Wp,
       const float* __restrict__ bproj,
       const bf16* __restrict__ Wp1, const float* __restrict__ bpi1,
       const float* __restrict__ W2, const float* __restrict__ b2,
       float* __restrict__ pi_out) {
    const int gb = blockIdx.x;
    const int tid = threadIdx.x, lane = tid & 31;

    if (gb < GEMM_BLKS) {
        // ================= split3 target GEMM (R10-proven body) ==============
        constexpr int BM = 128, BN = 128, BK = 32, WNC = 4;
        constexpr int WARP_M = 64, WARP_N = 32;
        constexpr int FM = 4, FN = 4;
        constexpr int LDA = BK + 8, LDB = BN + 8;             // 40, 136
        constexpr int ASTG = BM * LDA;                        // 5120
        constexpr int BSTG = BK * LDB;                        // 4352
        extern __shared__ __align__(16) char sm3[];
        bf16* Ahs = (bf16*)sm3;
        bf16* Als = Ahs + 2 * ASTG;
        bf16* Bhs = Als + 2 * ASTG;
        bf16* Bls = Bhs + 2 * BSTG;

        const int warp = tid >> 5;
        const int wm = warp / WNC, wn = warp % WNC;
        const int bm0 = (gb >> 2) * BM, bn0 = (gb & 3) * BN;
        constexpr int ACH = BM * BK / 8, BCH = BK * BN / 8;   // 512, 512

        float acc[FM][FN][4];
#pragma unroll
        for (int i = 0; i < FM; i++)
#pragma unroll
            for (int j = 0; j < FN; j++)
#pragma unroll
                for (int k = 0; k < 4; k++) acc[i][j][k] = 0.f;

        auto load_tiles = [&](int kt, int buf) {
            for (int c = tid; c < ACH; c += 256) {
                int r = c / 4, co = (c % 4) * 8;
                size_t g = (size_t)(bm0 + r) * CC + (size_t)kt * BK + co;
                cp_async16(smem_u32(Ahs + buf * ASTG + r * LDA + co), Ah + g);
                cp_async16(smem_u32(Als + buf * ASTG + r * LDA + co), Al + g);
            }
            for (int c = tid; c < BCH; c += 256) {
                int r = c / 16, co = (c % 16) * 8;
                size_t g = (size_t)(kt * BK + r) * CC + bn0 + co;
                cp_async16(smem_u32(Bhs + buf * BSTG + r * LDB + co), Bh + g);
                cp_async16(smem_u32(Bls + buf * BSTG + r * LDB + co), Bl + g);
            }
        };

        const int KTL = CC / BK;   // 16
        load_tiles(0, 0);
        cp_commit();
        for (int it = 0; it < KTL; ++it) {
            int buf = it & 1;
            cp_wait0();
            __syncthreads();
            if (it + 1 < KTL) {
                load_tiles(it + 1, buf ^ 1);
                cp_commit();
            }
#pragma unroll
            for (int kk = 0; kk < BK / 16; ++kk) {
                uint32_t ahf[FM][4], alf[FM][4], bhf[FN][2], blf[FN][2];
#pragma unroll
                for (int i = 0; i < FM; i++) {
                    int r = wm * WARP_M + i * 16 + (lane & 15);
                    int cc = kk * 16 + ((lane >> 4) << 3);
                    ldsm_x4(ahf[i], smem_u32(Ahs + buf * ASTG + r * LDA + cc));
                    ldsm_x4(alf[i], smem_u32(Als + buf * ASTG + r * LDA + cc));
                }
#pragma unroll
                for (int j = 0; j < FN; j++) {
                    int r = kk * 16 + (lane & 15);
                    int cc = wn * WARP_N + j * 8;
                    ldsm_x2t(bhf[j], smem_u32(Bhs + buf * BSTG + r * LDB + cc));
                    ldsm_x2t(blf[j], smem_u32(Bls + buf * BSTG + r * LDB + cc));
                }
#pragma unroll
                for (int i = 0; i < FM; i++)
#pragma unroll
                    for (int j = 0; j < FN; j++) {
                        mma_bf16(acc[i][j], ahf[i], bhf[j]);
                        mma_bf16(acc[i][j], ahf[i], blf[j]);
                        mma_bf16(acc[i][j], alf[i], bhf[j]);
                    }
            }
            __syncthreads();
        }

#pragma unroll
        for (int i = 0; i < FM; i++) {
            int rbase = bm0 + wm * WARP_M + i * 16 + (lane >> 2);
#pragma unroll
            for (int h = 0; h < 2; h++) {
                int r = rbase + h * 8;
#pragma unroll
                for (int j = 0; j < FN; j++) {
                    int c = bn0 + wn * WARP_N + j * 8 + (lane & 3) * 2;
                    float x0 = fmaxf(acc[i][j][h * 2 + 0] + bias[c], 0.f);
                    float x1 = fmaxf(acc[i][j][h * 2 + 1] + bias[c + 1], 0.f);
                    *reinterpret_cast<float2*>(outf + (size_t)r * CC + c) =
                        make_float2(x0, x1);
                }
            }
        }
        return;
    }

    if (gb < GEMM_BLKS + MLP_BLKS) {
        // ================= MLP -> pi (R7 body, /q deferred) ==================
        extern __shared__ __align__(16) char smm[];
        bf16* Zs = (bf16*)smm;              // [128][72]
        bf16* Xs = Zs + 128 * 72;           // [2][128][72]
        bf16* Ws = Xs + 2 * 128 * 72;       // [2][64][72]
        float* scal = (float*)(Ws + 2 * 64 * 72);  // [256]

        const int wm = tid >> 5;
        const int bm0 = (gb - GEMM_BLKS) * 128;

        float accz[8][4];
#pragma unroll
        for (int j = 0; j < 8; j++)
#pragma unroll
            for (int k = 0; k < 4; k++) accz[j][k] = 0.f;

        auto ld1 = [&](int kt, int buf) {
#pragma unroll
            for (int c0 = 0; c0 < 1024; c0 += 256) {
                int c = c0 + tid;
                int r = c >> 3, co = (c & 7) * 8;
                cp_async16(smem_u32(Xs + buf * 9216 + r * 72 + co),
                           X + (size_t)(bm0 + r) * CC + kt * 64 + co);
            }
#pragma unroll
            for (int c0 = 0; c0 < 512; c0 += 256) {
                int c = c0 + tid;
                int r = c >> 3, co = (c & 7) * 8;
                cp_async16(smem_u32(Ws + buf * 4608 + r * 72 + co),
                           Wp + (size_t)(kt * 64 + r) * LL + co);
            }
        };

        ld1(0, 0);
        cp_commit();
        for (int kt = 0; kt < 8; ++kt) {
            int buf = kt & 1;
            cp_wait0();
            __syncthreads();
            if (kt < 7) {
                ld1(kt + 1, buf ^ 1);
                cp_commit();
            }
#pragma unroll
            for (int kk = 0; kk < 4; ++kk) {
                uint32_t a[4];
                ldsm_x4(a, smem_u32(Xs + buf * 9216 + (wm * 16 + (lane & 15)) * 72 +
                                    kk * 16 + ((lane >> 4) << 3)));
#pragma unroll
                for (int j = 0; j < 8; j++) {
                    uint32_t b[2];
                    ldsm_x2t(b, smem_u32(Ws + buf * 4608 + (kk * 16 + (lane & 15)) * 72 + j * 8));
                    mma_bf16(accz[j], a, b);
                }
            }
            __syncthreads();
        }

#pragma unroll
        for (int j = 0; j < 8; j++)
#pragma unroll
            for (int h = 0; h < 2; h++) {
                int r = wm * 16 + (lane >> 2) + 8 * h;
                int c = j * 8 + (lane & 3) * 2;
                float z0 = accz[j][2 * h + 0] + bproj[c];
                float z1 = accz[j][2 * h + 1] + bproj[c + 1];
                *reinterpret_cast<__nv_bfloat162*>(Zs + r * 72 + c) =
                    __floats2bfloat162_rn(z0, z1);
            }
        __syncthreads();

        bf16* Bs2 = Xs;
        float pia[2] = {0.f, 0.f};
        for (int nt = 0; nt < 4; ++nt) {
            int n0 = nt * 128;
#pragma unroll
            for (int c0 = 0; c0 < 1024; c0 += 256) {
                int c = c0 + tid;
                int r = c >> 4, co = (c & 15) * 8;
                cp_async16(smem_u32(Bs2 + r * 136 + co),
                           Wp1 + (size_t)r * CC + n0 + co);
            }
            if (tid < 128) scal[tid] = bpi1[n0 + tid];
            else           scal[tid] = W2[n0 + tid - 128];
            cp_commit();
            cp_wait0();
            __syncthreads();

            float acc2[16][4];
#pragma unroll
            for (int j = 0; j < 16; j++)
#pragma unroll
                for (int k = 0; k < 4; k++) acc2[j][k] = 0.f;
#pragma unroll
            for (int kk = 0; kk < 4; ++kk) {
                uint32_t a[4];
                ldsm_x4(a, smem_u32(Zs + (wm * 16 + (lane & 15)) * 72 +
                                    kk * 16 + ((lane >> 4) << 3)));
#pragma unroll
                for (int j = 0; j < 16; j++) {
                    uint32_t b[2];
                    ldsm_x2t(b, smem_u32(Bs2 + (kk * 16 + (lane & 15)) * 136 + j * 8));
                    mma_bf16(acc2[j], a, b);
                }
            }
#pragma unroll
            for (int j = 0; j < 16; j++)
#pragma unroll
                for (int h = 0; h < 2; h++) {
                    int c = j * 8 + (lane & 3) * 2;
                    float h0 = fmaxf(acc2[j][2 * h + 0] + scal[c], 0.f);
                    float h1 = fmaxf(acc2[j][2 * h + 1] + scal[c + 1], 0.f);
                    pia[h] += h0 * scal[128 + c] + h1 * scal[128 + c + 1];
                }
            __syncthreads();
        }

#pragma unroll
        for (int h = 0; h < 2; h++) {
            pia[h] += __shfl_xor_sync(0xffffffffu, pia[h], 1);
            pia[h] += __shfl_xor_sync(0xffffffffu, pia[h], 2);
        }
        if ((lane & 3) == 0) {
            float bb = b2[0];
#pragma unroll
            for (int h = 0; h < 2; h++) {
                int row = bm0 + wm * 16 + (lane >> 2) + 8 * h;
                float s = pia[h] + bb;
                pi_out[row] = 1.f / (1.f + expf(-s));
            }
        }
        return;
    }

    // ================= adj rowsum + bf16 convert (DRAM-bound) ================
    {
        int row = gb - GEMM_BLKS - MLP_BLKS;
        const float4* src = reinterpret_cast<const float4*>(adj + (size_t)row * NN);
        uint2* dst = reinterpret_cast<uint2*>(adjb + (size_t)row * NN);
        float s = 0.f;
#pragma unroll
        for (int i = 0; i < 4; i++) {
            float4 f = src[tid + i * 256];
            s += (f.x + f.y) + (f.z + f.w);
            __nv_bfloat162 b0 = __floats2bfloat162_rn(f.x, f.y);
            __nv_bfloat162 b1 = __floats2bfloat162_rn(f.z, f.w);
            uint2 u;
            u.x = *reinterpret_cast<uint32_t*>(&b0);
            u.y = *reinterpret_cast<uint32_t*>(&b1);
            dst[tid + i * 256] = u;
        }
        for (int o = 16; o > 0; o >>= 1) s += __shfl_xor_sync(0xffffffffu, s, o);
        __shared__ float ws[8];
        if ((tid & 31) == 0) ws[tid >> 5] = s;
        __syncthreads();
        if (tid == 0) {
            float tot = 0.f;
#pragma unroll
            for (int i = 0; i < 8; i++) tot += ws[i];
            q[row] = tot;
        }
    }
}

// v[row] = pi[row]/q[row]; stb[row, :] = bf16(v[row] * target[row, :])
__global__ void k_vstb(const float* __restrict__ pi, const float* __restrict__ q,
                       float* __restrict__ v, const float* __restrict__ tgt,
                       bf16* __restrict__ stb) {
    int row = blockIdx.x, t = threadIdx.x;  // 128 threads
    float vr = pi[row] / q[row];
    if (t == 0) v[row] = vr;
    float4 f = reinterpret_cast<const float4*>(tgt + (size_t)row * CC)[t];
    __nv_bfloat162 b0 = __floats2bfloat162_rn(vr * f.x, vr * f.y);
    __nv_bfloat162 b1 = __floats2bfloat162_rn(vr * f.z, vr * f.w);
    uint2 u;
    u.x = *reinterpret_cast<uint32_t*>(&b0);
    u.y = *reinterpret_cast<uint32_t*>(&b1);
    reinterpret_cast<uint2*>(stb + (size_t)row * CC)[t] = u;
}

// d[i] = sum_j adjb[i,j] * v[j] + 1e-5
__global__ void k_dvec(const bf16* __restrict__ adjb, const float* __restrict__ v,
                       float* __restrict__ d) {
    int row = blockIdx.x, t = threadIdx.x;  // 256 threads
    const uint4* ap = reinterpret_cast<const uint4*>(adjb + (size_t)row * NN);
    float s = 0.f;
#pragma unroll
    for (int i = 0; i < 2; i++) {
        int ci = t + i * 256;
        uint4 u = ap[ci];
        const float4* vp = reinterpret_cast<const float4*>(v + ci * 8);
        float4 v0 = vp[0], v1 = vp[1];
        __nv_bfloat162 a0 = *reinterpret_cast<__nv_bfloat162*>(&u.x);
        __nv_bfloat162 a1 = *reinterpret_cast<__nv_bfloat162*>(&u.y);
        __nv_bfloat162 a2 = *reinterpret_cast<__nv_bfloat162*>(&u.z);
        __nv_bfloat162 a3 = *reinterpret_cast<__nv_bfloat162*>(&u.w);
        s += __bfloat162float(a0.x) * v0.x + __bfloat162float(a0.y) * v0.y +
             __bfloat162float(a1.x) * v0.z + __bfloat162float(a1.y) * v0.w +
             __bfloat162float(a2.x) * v1.x + __bfloat162float(a2.y) * v1.y +
             __bfloat162float(a3.x) * v1.z + __bfloat162float(a3.y) * v1.w;
    }
    for (int o = 16; o > 0; o >>= 1) s += __shfl_xor_sync(0xffffffffu, s, o);
    __shared__ float ws[8];
    if ((t & 31) == 0) ws[t >> 5] = s;
    __syncthreads();
    if (t == 0) {
        float tot = 0.f;
#pragma unroll
        for (int i = 0; i < 8; i++) tot += ws[i];
        d[row] = tot + 1e-5f;
    }
}

// ---------------- final GEMM (R10 winner; unchanged) -------------------------
__global__ void __launch_bounds__(128, 2)
k_final(const bf16* __restrict__ A, const bf16* __restrict__ B,
        const float* __restrict__ dvec, const float* __restrict__ tgt,
        const float* __restrict__ dtp, float* __restrict__ outf) {
    constexpr int BM = 128, BN = 64, BK = 64;
    constexpr int FM = 4, FN = 4;
    constexpr int LDA = BK + 8, LDB = BN + 8;             // 72, 72
    constexpr int ASTG = BM * LDA;                        // 9216
    constexpr int BSTG = BK * LDB;                        // 4608
    extern __shared__ __align__(16) char smf[];
    bf16* As = (bf16*)smf;               // [3][ASTG]
    bf16* Bs = As + 3 * ASTG;            // [3][BSTG]

    const int tid = threadIdx.x, lane = tid & 31, warp = tid >> 5;
    const int wm = warp >> 1, wn = warp & 1;
    const int bm0 = blockIdx.x * BM, bn0 = blockIdx.y * BN;
    constexpr int ACH = BM * BK / 8, BCH = BK * BN / 8;   // 1024, 512

    float acc[FM][FN][4];
#pragma unroll
    for (int i = 0; i < FM; i++)
#pragma unroll
        for (int j = 0; j < FN; j++)
#pragma unroll
            for (int k = 0; k < 4; k++) acc[i][j][k] = 0.f;

    auto load_tiles = [&](int kt, int buf) {
#pragma unroll
        for (int c0 = 0; c0 < ACH; c0 += 128) {
            int c = c0 + tid;
            int r = c / 8, co = (c % 8) * 8;
            cp_async16(smem_u32(As + buf * ASTG + r * LDA + co),
                       A + (size_t)(bm0 + r) * NN + (size_t)kt * BK + co);
        }
#pragma unroll
        for (int c0 = 0; c0 < BCH; c0 += 128) {
            int c = c0 + tid;
            int r = c / 8, co = (c % 8) * 8;
            cp_async16(smem_u32(Bs + buf * BSTG + r * LDB + co),
                       B + (size_t)(kt * BK + r) * CC + bn0 + co);
        }
    };

    const int KTL = NN / BK;   // 64
    load_tiles(0, 0); cp_commit();
    load_tiles(1, 1); cp_commit();

    for (int it = 0; it < KTL; ++it) {
        int buf = it % 3;
        if (it + 1 < KTL) cp_wait1();
        else              cp_wait0();
        __syncthreads();
        if (it + 2 < KTL) {
            load_tiles(it + 2, (it + 2) % 3);
            cp_commit();
        }
#pragma unroll
        for (int kk = 0; kk < BK / 16; ++kk) {
            uint32_t af[FM][4], bfr[FN][2];
#pragma unroll
            for (int i = 0; i < FM; i++) {
                int r = wm * 64 + i * 16 + (lane & 15);
                int cc = kk * 16 + ((lane >> 4) << 3);
                ldsm_x4(af[i], smem_u32(As + buf * ASTG + r * LDA + cc));
            }
#pragma unroll
            for (int j = 0; j < FN; j++) {
                int r = kk * 16 + (lane & 15);
                int cc = wn * 32 + j * 8;
                ldsm_x2t(bfr[j], smem_u32(Bs + buf * BSTG + r * LDB + cc));
            }
#pragma unroll
            for (int i = 0; i < FM; i++)
#pragma unroll
                for (int j = 0; j < FN; j++) mma_bf16(acc[i][j], af[i], bfr[j]);
        }
        __syncthreads();
    }

    const float dt1 = dtp[0];
    const float mdt = 1.f - dt1;
#pragma unroll
    for (int i = 0; i < FM; i++) {
        int rbase = bm0 + wm * 64 + i * 16 + (lane >> 2);
#pragma unroll
        for (int h = 0; h < 2; h++) {
            int r = rbase + h * 8;
            float rs = dt1 / (0.25f * dvec[r]);
#pragma unroll
            for (int j = 0; j < FN; j++) {
                int c = bn0 + wn * 32 + j * 8 + (lane & 3) * 2;
                size_t idx = (size_t)r * CC + c;
                float2 tg = *reinterpret_cast<const float2*>(tgt + idx);
                float2 o;
                o.x = mdt * tg.x + rs * acc[i][j][h * 2 + 0];
                o.y = mdt * tg.y + rs * acc[i][j][h * 2 + 1];
                *reinterpret_cast<float2*>(outf + idx) = o;
            }
        }
    }
}

// ---------------- host -------------------------------------------------------
extern "C" void kernel_launch(void* const* d_in, const int* in_sizes, int n_in,
                              void* d_out, int out_size) {
    const float* x      = (const float*)d_in[0];
    const float* adj    = (const float*)d_in[1];
    const float* W_proj = (const float*)d_in[2];
    const float* b_proj = (const float*)d_in[3];
    const float* W_pi1  = (const float*)d_in[4];
    const float* b_pi1  = (const float*)d_in[5];
    const float* W_pi2  = (const float*)d_in[6];
    const float* b_pi2  = (const float*)d_in[7];
    const float* W_f    = (const float*)d_in[8];
    const float* b_f    = (const float*)d_in[9];
    const float* dt     = (const float*)d_in[10];
    float* out = (float*)d_out;
    (void)in_sizes; (void)n_in; (void)out_size;

    void *p_adjb, *p_xhi, *p_xlo, *p_wfhi, *p_wflo, *p_wprojb, *p_wpi1b;
    void *p_stb, *p_tgt, *p_q, *p_pi, *p_v, *p_d;
    cudaGetSymbolAddress(&p_adjb, g_adjb);
    cudaGetSymbolAddress(&p_xhi, g_Xhi);
    cudaGetSymbolAddress(&p_xlo, g_Xlo);
    cudaGetSymbolAddress(&p_wfhi, g_Wfhi);
    cudaGetSymbolAddress(&p_wflo, g_Wflo);
    cudaGetSymbolAddress(&p_wprojb, g_Wprojb);
    cudaGetSymbolAddress(&p_wpi1b, g_Wpi1b);
    cudaGetSymbolAddress(&p_stb, g_stb);
    cudaGetSymbolAddress(&p_tgt, g_target);
    cudaGetSymbolAddress(&p_q, g_q);
    cudaGetSymbolAddress(&p_pi, g_pi);
    cudaGetSymbolAddress(&p_v, g_v);
    cudaGetSymbolAddress(&p_d, g_d);

    bf16* adjb = (bf16*)p_adjb;
    bf16 *Xhi = (bf16*)p_xhi, *Xlo = (bf16*)p_xlo;
    bf16 *Wfhi = (bf16*)p_wfhi, *Wflo = (bf16*)p_wflo;
    bf16 *Wprojb = (bf16*)p_wprojb, *Wpi1b = (bf16*)p_wpi1b;
    bf16 *stb = (bf16*)p_stb;
    float *tgt = (float*)p_tgt, *q = (float*)p_q, *pi = (float*)p_pi;
    float *v = (float*)p_v, *d = (float*)p_d;

    // dynamic smem opt-ins (idempotent). Mega uses max(split3, mlp) smem.
    const int SMG = 76800;                 // >= 75,776 (split3) and 74,752+pad (mlp)
    const int SMF = 3 * (9216 + 4608) * 2; // 82,944 B
    cudaFuncSetAttribute(k_mega, cudaFuncAttributeMaxDynamicSharedMemorySize, SMG);
    cudaFuncSetAttribute(k_final, cudaFuncAttributeMaxDynamicSharedMemorySize, SMF);

    // 1. tiny conversions (x split, W_f split, W_proj, W_pi1)
    {
        const int tot = NN * CC + CC * CC + CC * LL + LL * CC;
        k_conv<<<(tot + 255) / 256, 256>>>(x, W_f, W_proj, W_pi1,
                                           Xhi, Xlo, Wfhi, Wflo, Wprojb, Wpi1b);
    }

    // 2. MEGA: target-GEMM (tensor) + MLP->pi (tensor) + adj rowsum/convert (DRAM)
    k_mega<<<GEMM_BLKS + MLP_BLKS + NN, 256, SMG>>>(
        adj, adjb, q,
        Xhi, Xlo, Wfhi, Wflo, b_f, tgt,
        Xhi, Wprojb, b_proj, Wpi1b, b_pi1, W_pi2, b_pi2, pi);

    // 3. v = pi/q; stb = bf16(v * target)
    k_vstb<<<NN, 128>>>(pi, q, v, tgt, stb);

    // 4. d = adjb @ v + 1e-5
    k_dvec<<<NN, 256>>>(adjb, v, d);

    // 5. out = (1-dt)*target + (dt/(eps*d[m])) * (adjb @ stb)
    k_final<<<dim3(NN / 128, CC / 64), 128, SMF>>>(adjb, stb, d, tgt, dt, out);
}